// round 8
// baseline (speedup 1.0000x reference)
#include <cuda_runtime.h>
#include <cuda_bf16.h>
#include <cstdint>

// ---------------------------------------------------------------------------
// Problem constants
// ---------------------------------------------------------------------------
static constexpr int E_  = 8;
static constexpr int H_  = 1024;
static constexpr int FF_ = 4096;
static constexpr int T_  = 32768;
static constexpr int G_  = T_ / E_;       // 4096 tokens per expert

static constexpr float QMAXF = 16256.f;   // 127*128
static constexpr float HMAX  = 5.0f;      // fixed bound for |h|
static constexpr float DH    = HMAX / QMAXF;          // h quant step
static constexpr float INV_DH = QMAXF / HMAX;

// GEMM tiling: CTA 128x128 int8, 8 warps (4 M x 2 N), warp tile 32x64, BK=64
static constexpr int BM = 128;
static constexpr int BN = 128;
static constexpr int BK = 64;             // int8 elems per K-stage (2 x k32)
static constexpr int PITCH = 80;          // 64B data + 16B pad
static constexpr int OFF_A1 = BM * PITCH;            // 10240
static constexpr int OFF_B0 = 2 * BM * PITCH;        // 20480
static constexpr int OFF_B1 = OFF_B0 + BN * PITCH;   // 30720
static constexpr int STAGE_BYTES = OFF_B1 + BN * PITCH;  // 40960
static constexpr int NSTAGE = 3;
static constexpr int SMEM_TOTAL = NSTAGE * STAGE_BYTES;  // 122880
static constexpr int NTHREADS = 256;

// ---------------------------------------------------------------------------
// Device scratch
// ---------------------------------------------------------------------------
__device__ int8_t  g_X0[(size_t)T_ * H_];
__device__ int8_t  g_X1[(size_t)T_ * H_];
__device__ int8_t  g_W10[(size_t)E_ * FF_ * H_];
__device__ int8_t  g_W11[(size_t)E_ * FF_ * H_];
__device__ int8_t  g_W2T0[(size_t)E_ * H_ * FF_];
__device__ int8_t  g_W2T1[(size_t)E_ * H_ * FF_];
__device__ int8_t  g_H0[(size_t)T_ * FF_];
__device__ int8_t  g_H1[(size_t)T_ * FF_];
__device__ float    g_SX[T_];          // x row quant steps (delta)
__device__ float    g_SW1[E_ * FF_];   // w1 row quant steps
__device__ uint32_t g_SW2B[E_ * H_];   // w2 column absmax (float bits)

// ---------------------------------------------------------------------------
// PTX helpers (family-safe: sm_80-era)
// ---------------------------------------------------------------------------
__device__ __forceinline__ uint32_t smem_u32(const void* p) {
    uint32_t a;
    asm("{ .reg .u64 t; cvta.to.shared.u64 t, %1; cvt.u32.u64 %0, t; }" : "=r"(a) : "l"(p));
    return a;
}
__device__ __forceinline__ void cp16(uint32_t dst, const void* src) {
    asm volatile("cp.async.cg.shared.global [%0], [%1], 16;" :: "r"(dst), "l"(src) : "memory");
}
#define CP_COMMIT() asm volatile("cp.async.commit_group;" ::: "memory")
#define CP_WAIT1()  asm volatile("cp.async.wait_group 1;" ::: "memory")

__device__ __forceinline__ void ldsm4(uint32_t& r0, uint32_t& r1, uint32_t& r2, uint32_t& r3,
                                      uint32_t addr) {
    asm volatile("ldmatrix.sync.aligned.m8n8.x4.shared.b16 {%0,%1,%2,%3}, [%4];"
                 : "=r"(r0), "=r"(r1), "=r"(r2), "=r"(r3) : "r"(addr));
}
// int8 MMA: m16n8k32 s8*s8 -> s32
__device__ __forceinline__ void imma(int* d, const uint32_t* a, const uint32_t* b) {
    asm volatile(
        "mma.sync.aligned.m16n8k32.row.col.s32.s8.s8.s32 "
        "{%0,%1,%2,%3}, {%4,%5,%6,%7}, {%8,%9}, {%0,%1,%2,%3};"
        : "+r"(d[0]), "+r"(d[1]), "+r"(d[2]), "+r"(d[3])
        : "r"(a[0]), "r"(a[1]), "r"(a[2]), "r"(a[3]), "r"(b[0]), "r"(b[1]));
}

// split q (|q|<=16256) into hi/lo chunks: q = 128*Q0 + Q1, Q1 in [-64,63]
__device__ __forceinline__ void chunk2(int q, int8_t& c0, int8_t& c1) {
    int q0 = (q + 64) >> 7;      // arithmetic shift = floor div
    c0 = (int8_t)q0;
    c1 = (int8_t)(q - (q0 << 7));
}

// ---------------------------------------------------------------------------
// Quantization kernels
// ---------------------------------------------------------------------------
// rows of length 1024: per-row absmax scale, 2-chunk int8. 256 thr = 4 elems each.
__global__ void rowquant_1024(const float* __restrict__ in,
                              int8_t* __restrict__ p0, int8_t* __restrict__ p1,
                              float* __restrict__ dscale) {
    const int r = blockIdx.x;
    const int tid = threadIdx.x;
    const float4 v = reinterpret_cast<const float4*>(in + (size_t)r * 1024)[tid];
    float m = fmaxf(fmaxf(fabsf(v.x), fabsf(v.y)), fmaxf(fabsf(v.z), fabsf(v.w)));
    __shared__ float red[256];
    red[tid] = m; __syncthreads();
#pragma unroll
    for (int s = 128; s > 0; s >>= 1) {
        if (tid < s) red[tid] = fmaxf(red[tid], red[tid + s]);
        __syncthreads();
    }
    const float rmax = fmaxf(red[0], 1e-20f);
    const float inv = QMAXF / rmax;
    if (tid == 0) dscale[r] = rmax / QMAXF;
    int q0 = __float2int_rn(v.x * inv), q1 = __float2int_rn(v.y * inv);
    int q2 = __float2int_rn(v.z * inv), q3 = __float2int_rn(v.w * inv);
    char4 a, b;
    chunk2(q0, (int8_t&)a.x, (int8_t&)b.x); chunk2(q1, (int8_t&)a.y, (int8_t&)b.y);
    chunk2(q2, (int8_t&)a.z, (int8_t&)b.z); chunk2(q3, (int8_t&)a.w, (int8_t&)b.w);
    reinterpret_cast<char4*>(p0 + (size_t)r * 1024)[tid] = a;
    reinterpret_cast<char4*>(p1 + (size_t)r * 1024)[tid] = b;
}

__global__ void zero_sw2b() {
    int i = blockIdx.x * blockDim.x + threadIdx.x;
    if (i < E_ * H_) g_SW2B[i] = 0u;
}

// column absmax of w2 [E, FF, H] over FF (per (e,h))
__global__ void w2_absmax(const float* __restrict__ w2) {
    const int e = blockIdx.z;
    const int h = blockIdx.y * 32 + (threadIdx.x & 31);
    const int fg = threadIdx.x >> 5;  // 0..7
    const int f0 = blockIdx.x * 256 + fg * 32;
    float m = 0.f;
#pragma unroll 8
    for (int i = 0; i < 32; i++) {
        m = fmaxf(m, fabsf(w2[(size_t)e * FF_ * H_ + (size_t)(f0 + i) * H_ + h]));
    }
    __shared__ float sm[8][32];
    sm[fg][threadIdx.x & 31] = m; __syncthreads();
    if (fg == 0) {
#pragma unroll
        for (int k = 1; k < 8; k++) m = fmaxf(m, sm[k][threadIdx.x & 31]);
        atomicMax(&g_SW2B[e * H_ + h], __float_as_uint(m));
    }
}

// transpose + quantize w2 [E,FF,H] -> planes [E,H,FF]
__global__ void w2_transquant(const float* __restrict__ w2) {
    __shared__ float t[32][33];
    const int e  = blockIdx.z;
    const int h0 = blockIdx.x * 32;
    const int f0 = blockIdx.y * 32;
    const float* src = w2 + (size_t)e * FF_ * H_;
#pragma unroll
    for (int j = 0; j < 4; j++)
        t[threadIdx.y + j * 8][threadIdx.x] =
            src[(size_t)(f0 + threadIdx.y + j * 8) * H_ + h0 + threadIdx.x];
    __syncthreads();
#pragma unroll
    for (int j = 0; j < 4; j++) {
        const int h = h0 + threadIdx.y + j * 8;
        const int f = f0 + threadIdx.x;
        const float rmax = fmaxf(__uint_as_float(g_SW2B[e * H_ + h]), 1e-20f);
        const float inv = QMAXF / rmax;
        const float val = t[threadIdx.x][threadIdx.y + j * 8];
        int q = __float2int_rn(val * inv);
        int8_t c0, c1; chunk2(q, c0, c1);
        const size_t idx = ((size_t)e * H_ + h) * FF_ + f;
        g_W2T0[idx] = c0; g_W2T1[idx] = c1;
    }
}

// ---------------------------------------------------------------------------
// int8 TN grouped GEMM: C = A @ B^T with A,B 2-chunk int8.
// combined = 16384*P00 + 128*(P01+P10)   (P11 dropped, ~1.5e-4)
// CTA 128x128, 8 warps (4M x 2N), warp 32x64, BK=64 (2 x k32 IMMA steps).
// MODE 0: out = relu(sx_r*sw_c*comb) -> quantize to h planes (fixed DH)
// MODE 1: out = DH*sw2_c*comb -> fp32 store
// ---------------------------------------------------------------------------
template <int KDIM, int MODE>
__global__ void __launch_bounds__(NTHREADS, 1)
gemm_s8(const int8_t* __restrict__ A0, const int8_t* __restrict__ A1, int lda,
        const int8_t* __restrict__ B0, const int8_t* __restrict__ B1, int ldb,
        int bExpStride,
        const float* __restrict__ sxArr,       // MODE0 row scales
        const float* __restrict__ sw1Arr,      // MODE0 col scales (delta)
        int8_t* __restrict__ H0, int8_t* __restrict__ H1,   // MODE0 outputs
        float* __restrict__ Cf) {              // MODE1 output
    extern __shared__ char smem[];
    const uint32_t sbase = smem_u32(smem);
    const int tid  = threadIdx.x;
    const int lane = tid & 31;
    const int warp = tid >> 5;
    const int wm = warp & 3;            // 0..3 (M, 32 rows)
    const int wn = warp >> 2;           // 0..1 (N, 64 cols)
    const int aRow0 = blockIdx.z * G_ + blockIdx.y * BM;
    const int bRow0 = blockIdx.z * bExpStride + blockIdx.x * BN;
    const int col0  = blockIdx.x * BN;
    constexpr int S = KDIM / BK;

    int acc00[2][8][4], accmx[2][8][4];
#pragma unroll
    for (int i = 0; i < 2; i++)
#pragma unroll
        for (int j = 0; j < 8; j++)
#pragma unroll
            for (int q = 0; q < 4; q++) { acc00[i][j][q] = 0; accmx[i][j][q] = 0; }

    // stage loader: 4 planes x 512 chunks(16B) = 2048 -> 8 cp16/thread
    auto load_stage = [&](int s, int buf) {
        const uint32_t st = sbase + buf * STAGE_BYTES;
        const int k0 = s * BK;
#pragma unroll
        for (int i = 0; i < 2; i++) {
            int c = tid + i * NTHREADS;
            int r = c >> 2, q = c & 3;
            uint32_t so = (uint32_t)(r * PITCH + q * 16);
            size_t ga = (size_t)(aRow0 + r) * lda + k0 + q * 16;
            cp16(st + so,          A0 + ga);
            cp16(st + OFF_A1 + so, A1 + ga);
            size_t gb = (size_t)(bRow0 + r) * ldb + k0 + q * 16;
            cp16(st + OFF_B0 + so, B0 + gb);
            cp16(st + OFF_B1 + so, B1 + gb);
        }
    };

    // lane-fixed ldmatrix address parts (rows of 64B, pitch 80)
    const uint32_t aLane = (uint32_t)((wm * 32 + (lane & 15)) * PITCH + (lane >> 4) * 16);
    const uint32_t bLane = (uint32_t)((wn * 64 + (lane & 15)) * PITCH + (lane >> 4) * 16);

    load_stage(0, 0); CP_COMMIT();
    load_stage(1, 1); CP_COMMIT();

    for (int s = 0; s < S; s++) {
        CP_WAIT1();                 // stage s resident (1 younger group pending)
        __syncthreads();            // single barrier: all warps past compute(s-1)
        if (s + 2 < S) load_stage(s + 2, (s + 2) % NSTAGE);
        CP_COMMIT();                // always commit (possibly empty group)

        const uint32_t st = sbase + (s % NSTAGE) * STAGE_BYTES;
#pragma unroll
        for (int ks = 0; ks < 2; ks++) {             // two k32 steps per stage
            const uint32_t kOff = (uint32_t)(ks * 32);
            uint32_t a0[2][4], a1[2][4], bx[8][2];
#pragma unroll
            for (int ib = 0; ib < 2; ib++) {
                uint32_t ad = st + aLane + kOff + (uint32_t)(ib * 16 * PITCH);
                ldsm4(a0[ib][0], a0[ib][1], a0[ib][2], a0[ib][3], ad);
                ldsm4(a1[ib][0], a1[ib][1], a1[ib][2], a1[ib][3], ad + OFF_A1);
            }
#pragma unroll
            for (int jj = 0; jj < 4; jj++) {         // bx <- B0
                uint32_t bd = st + OFF_B0 + bLane + kOff + (uint32_t)(jj * 16 * PITCH);
                uint32_t r0, r1, r2, r3;
                ldsm4(r0, r1, r2, r3, bd);
                bx[jj * 2 + 0][0] = r0; bx[jj * 2 + 1][0] = r1;
                bx[jj * 2 + 0][1] = r2; bx[jj * 2 + 1][1] = r3;
            }
#pragma unroll
            for (int i = 0; i < 2; i++)
#pragma unroll
                for (int j = 0; j < 8; j++) imma(acc00[i][j], a0[i], bx[j]);  // P00
#pragma unroll
            for (int i = 0; i < 2; i++)
#pragma unroll
                for (int j = 0; j < 8; j++) imma(accmx[i][j], a1[i], bx[j]);  // P10
#pragma unroll
            for (int jj = 0; jj < 4; jj++) {         // bx <- B1 (reuse regs)
                uint32_t bd = st + OFF_B1 + bLane + kOff + (uint32_t)(jj * 16 * PITCH);
                uint32_t r0, r1, r2, r3;
                ldsm4(r0, r1, r2, r3, bd);
                bx[jj * 2 + 0][0] = r0; bx[jj * 2 + 1][0] = r1;
                bx[jj * 2 + 0][1] = r2; bx[jj * 2 + 1][1] = r3;
            }
#pragma unroll
            for (int i = 0; i < 2; i++)
#pragma unroll
                for (int j = 0; j < 8; j++) imma(accmx[i][j], a0[i], bx[j]);  // P01
        }
    }
    __syncthreads();   // protect smem (not reused, but keep warps together for exit)

    // ---- epilogue ----------------------------------------------------------
    const int rBase = aRow0 + wm * 32 + (lane >> 2);
    const int cBase = col0 + wn * 64 + 2 * (lane & 3);
    if (MODE == 0) {
        float sxv[2][2];
#pragma unroll
        for (int i = 0; i < 2; i++) {
            sxv[i][0] = sxArr[rBase + i * 16];
            sxv[i][1] = sxArr[rBase + i * 16 + 8];
        }
        const int csBase = blockIdx.z * FF_ + cBase;
#pragma unroll
        for (int j = 0; j < 8; j++) {
            const float sw0 = sw1Arr[csBase + j * 8];
            const float sw1v = sw1Arr[csBase + j * 8 + 1];
#pragma unroll
            for (int i = 0; i < 2; i++) {
#pragma unroll
                for (int half = 0; half < 2; half++) {
                    const int r = rBase + i * 16 + half * 8;
                    const float sc = sxv[i][half];
                    float v0 = sc * sw0  * (16384.f * (float)acc00[i][j][half*2+0]
                                            + 128.f * (float)accmx[i][j][half*2+0]);
                    float v1 = sc * sw1v * (16384.f * (float)acc00[i][j][half*2+1]
                                            + 128.f * (float)accmx[i][j][half*2+1]);
                    v0 = fmaxf(v0, 0.f); v1 = fmaxf(v1, 0.f);
                    int q0 = min(__float2int_rn(v0 * INV_DH), 16256);
                    int q1 = min(__float2int_rn(v1 * INV_DH), 16256);
                    int8_t h00, h01, h10, h11;
                    chunk2(q0, h00, h10); chunk2(q1, h01, h11);
                    const size_t w = (size_t)r * FF_ + cBase + j * 8;
                    char2 p0; p0.x = h00; p0.y = h01;
                    char2 p1; p1.x = h10; p1.y = h11;
                    *reinterpret_cast<char2*>(H0 + w) = p0;
                    *reinterpret_cast<char2*>(H1 + w) = p1;
                }
            }
        }
    } else {
        const int csBase = blockIdx.z * H_ + cBase;
#pragma unroll
        for (int j = 0; j < 8; j++) {
            const float sw0  = DH * (__uint_as_float(g_SW2B[csBase + j * 8])     / QMAXF);
            const float sw1v = DH * (__uint_as_float(g_SW2B[csBase + j * 8 + 1]) / QMAXF);
#pragma unroll
            for (int i = 0; i < 2; i++) {
#pragma unroll
                for (int half = 0; half < 2; half++) {
                    const int r = rBase + i * 16 + half * 8;
                    float v0 = sw0  * (16384.f * (float)acc00[i][j][half*2+0]
                                       + 128.f * (float)accmx[i][j][half*2+0]);
                    float v1 = sw1v * (16384.f * (float)acc00[i][j][half*2+1]
                                       + 128.f * (float)accmx[i][j][half*2+1]);
                    float2 p = make_float2(v0, v1);
                    *reinterpret_cast<float2*>(&Cf[(size_t)r * H_ + cBase + j * 8]) = p;
                }
            }
        }
    }
}

// ---------------------------------------------------------------------------
// Host launcher
// ---------------------------------------------------------------------------
extern "C" void kernel_launch(void* const* d_in, const int* in_sizes, int n_in,
                              void* d_out, int out_size) {
    (void)in_sizes; (void)n_in; (void)out_size;
    const float* x  = (const float*)d_in[0];
    const float* w1 = (const float*)d_in[1];
    const float* w2 = (const float*)d_in[2];
    float* out = (float*)d_out;

    void *x0, *x1, *w10, *w11, *w2t0, *w2t1, *h0, *h1, *sx, *sw1;
    cudaGetSymbolAddress(&x0, g_X0);     cudaGetSymbolAddress(&x1, g_X1);
    cudaGetSymbolAddress(&w10, g_W10);   cudaGetSymbolAddress(&w11, g_W11);
    cudaGetSymbolAddress(&w2t0, g_W2T0); cudaGetSymbolAddress(&w2t1, g_W2T1);
    cudaGetSymbolAddress(&h0, g_H0);     cudaGetSymbolAddress(&h1, g_H1);
    cudaGetSymbolAddress(&sx, g_SX);     cudaGetSymbolAddress(&sw1, g_SW1);

    cudaFuncSetAttribute(gemm_s8<1024, 0>,
                         cudaFuncAttributeMaxDynamicSharedMemorySize, SMEM_TOTAL);
    cudaFuncSetAttribute(gemm_s8<4096, 1>,
                         cudaFuncAttributeMaxDynamicSharedMemorySize, SMEM_TOTAL);

    // 1) quantization
    rowquant_1024<<<T_, 256>>>(x, (int8_t*)x0, (int8_t*)x1, (float*)sx);
    rowquant_1024<<<E_ * FF_, 256>>>(w1, (int8_t*)w10, (int8_t*)w11, (float*)sw1);
    zero_sw2b<<<(E_ * H_ + 255) / 256, 256>>>();
    w2_absmax<<<dim3(FF_ / 256, H_ / 32, E_), 256>>>(w2);
    w2_transquant<<<dim3(H_ / 32, FF_ / 32, E_), dim3(32, 8)>>>(w2);

    // 2) GEMM1: h = relu(x @ w1^T) -> int8 planes; A ld=H, B ld=H, expstride FF
    gemm_s8<1024, 0><<<dim3(FF_ / BN, G_ / BM, E_), NTHREADS, SMEM_TOTAL>>>(
        (const int8_t*)x0, (const int8_t*)x1, H_,
        (const int8_t*)w10, (const int8_t*)w11, H_, FF_,
        (const float*)sx, (const float*)sw1,
        (int8_t*)h0, (int8_t*)h1, nullptr);

    // 3) GEMM2: out = h @ w2 (w2t planes); A ld=FF, B ld=FF, expstride H
    gemm_s8<4096, 1><<<dim3(H_ / BN, G_ / BM, E_), NTHREADS, SMEM_TOTAL>>>(
        (const int8_t*)h0, (const int8_t*)h1, FF_,
        (const int8_t*)w2t0, (const int8_t*)w2t1, FF_, H_,
        nullptr, nullptr,
        nullptr, nullptr, out);
}

// round 10
// speedup vs baseline: 5.0655x; 5.0655x over previous
#include <cuda_runtime.h>
#include <cuda_fp16.h>
#include <cstdint>

// ---------------------------------------------------------------------------
// Problem constants
// ---------------------------------------------------------------------------
static constexpr int E_  = 8;
static constexpr int H_  = 1024;
static constexpr int FF_ = 4096;
static constexpr int T_  = 32768;
static constexpr int G_  = T_ / E_;     // 4096 tokens per expert

// GEMM tiling: CTA 128x256, 16 warps (4 M x 4 N), warp tile 32x64, BK=32
static constexpr int BM = 128;
static constexpr int BN = 256;
static constexpr int BK = 32;           // fp16 elems per K-stage
static constexpr int PITCH = 80;        // SMEM row pitch bytes (64B data + 16B pad)
static constexpr int OFF_B = BM * PITCH;                  // 10240
static constexpr int STAGE_BYTES = OFF_B + BN * PITCH;    // 30720
static constexpr int NSTAGE = 3;
static constexpr int SMEM_TOTAL = NSTAGE * STAGE_BYTES;   // 92160
static constexpr int NTHREADS = 512;

// ---------------------------------------------------------------------------
// Device scratch
// ---------------------------------------------------------------------------
__device__ __half g_XH[(size_t)T_ * H_];
__device__ __half g_W1H[(size_t)E_ * FF_ * H_];
__device__ __half g_W2TH[(size_t)E_ * H_ * FF_];
__device__ __half g_HH[(size_t)T_ * FF_];

// ---------------------------------------------------------------------------
// PTX helpers (family-safe: sm_80-era instructions only)
// ---------------------------------------------------------------------------
__device__ __forceinline__ uint32_t smem_u32(const void* p) {
    uint32_t a;
    asm("{ .reg .u64 t; cvta.to.shared.u64 t, %1; cvt.u32.u64 %0, t; }" : "=r"(a) : "l"(p));
    return a;
}
__device__ __forceinline__ void cp16(uint32_t dst, const void* src) {
    asm volatile("cp.async.cg.shared.global [%0], [%1], 16;" :: "r"(dst), "l"(src) : "memory");
}
#define CP_COMMIT() asm volatile("cp.async.commit_group;" ::: "memory")
#define CP_WAIT2()  asm volatile("cp.async.wait_group 2;" ::: "memory")

__device__ __forceinline__ void ldsm4(uint32_t& r0, uint32_t& r1, uint32_t& r2, uint32_t& r3,
                                      uint32_t addr) {
    asm volatile("ldmatrix.sync.aligned.m8n8.x4.shared.b16 {%0,%1,%2,%3}, [%4];"
                 : "=r"(r0), "=r"(r1), "=r"(r2), "=r"(r3) : "r"(addr));
}
__device__ __forceinline__ void mma16816(float* d, const uint32_t* a, const uint32_t* b) {
    asm volatile(
        "mma.sync.aligned.m16n8k16.row.col.f32.f16.f16.f32 "
        "{%0,%1,%2,%3}, {%4,%5,%6,%7}, {%8,%9}, {%0,%1,%2,%3};"
        : "+f"(d[0]), "+f"(d[1]), "+f"(d[2]), "+f"(d[3])
        : "r"(a[0]), "r"(a[1]), "r"(a[2]), "r"(a[3]), "r"(b[0]), "r"(b[1]));
}

__device__ __forceinline__ uint32_t pack2h(__half a, __half b) {
    __half2 p = __halves2half2(a, b);
    return *reinterpret_cast<uint32_t*>(&p);
}

// ---------------------------------------------------------------------------
// fp32 -> fp16 cast kernels
// ---------------------------------------------------------------------------
__global__ void tohalf_kernel(const float* __restrict__ in,
                              __half* __restrict__ out, int n4) {
    for (int i = blockIdx.x * blockDim.x + threadIdx.x; i < n4; i += gridDim.x * blockDim.x) {
        float4 v = reinterpret_cast<const float4*>(in)[i];
        uint2 p;
        p.x = pack2h(__float2half(v.x), __float2half(v.y));
        p.y = pack2h(__float2half(v.z), __float2half(v.w));
        reinterpret_cast<uint2*>(out)[i] = p;
    }
}

// w2 [E, FF, H] -> w2t [E, H, FF] fp16, 32x32 SMEM tile transpose
__global__ void transpose_half(const float* __restrict__ in,
                               __half* __restrict__ outh) {
    __shared__ float t[32][33];
    const int e  = blockIdx.z;
    const int h0 = blockIdx.x * 32;
    const int f0 = blockIdx.y * 32;
    const float* src = in + (size_t)e * FF_ * H_;
#pragma unroll
    for (int j = 0; j < 4; j++)
        t[threadIdx.y + j * 8][threadIdx.x] =
            src[(size_t)(f0 + threadIdx.y + j * 8) * H_ + h0 + threadIdx.x];
    __syncthreads();
    __half* dh = outh + (size_t)e * H_ * FF_;
#pragma unroll
    for (int j = 0; j < 4; j++) {
        float v = t[threadIdx.x][threadIdx.y + j * 8];
        dh[(size_t)(h0 + threadIdx.y + j * 8) * FF_ + f0 + threadIdx.x] = __float2half(v);
    }
}

// ---------------------------------------------------------------------------
// TN grouped GEMM: C[M,N] = A[M,K] @ B[N,K]^T, fp16 single-term, fp32 accum.
// CTA tile 128x256; 16 warps as 4(M) x 4(N); warp tile 32x64; mma m16n8k16.
// MODE 0: epilogue = relu -> fp16 store into Hc (pitch FF_)
// MODE 1: epilogue = fp32 store into Cf (pitch H_)
// ---------------------------------------------------------------------------
template <int KDIM, int MODE>
__global__ void __launch_bounds__(NTHREADS, 1)
gemm_h1(const __half* __restrict__ A, int lda,
        const __half* __restrict__ B, int ldb, int bExpStride,
        __half* __restrict__ Hc, float* __restrict__ Cf) {
    extern __shared__ char smem[];
    const uint32_t sbase = smem_u32(smem);
    const int tid  = threadIdx.x;
    const int lane = tid & 31;
    const int warp = tid >> 5;
    const int wm = warp & 3;           // 0..3 (M, 32 rows each)
    const int wn = warp >> 2;          // 0..3 (N, 64 cols each)
    const int aRow0 = blockIdx.z * G_ + blockIdx.y * BM;
    const int bRow0 = blockIdx.z * bExpStride + blockIdx.x * BN;
    const int col0  = blockIdx.x * BN;
    constexpr int S = KDIM / BK;

    float acc[2][8][4];
#pragma unroll
    for (int i = 0; i < 2; i++)
#pragma unroll
        for (int j = 0; j < 8; j++)
#pragma unroll
            for (int q = 0; q < 4; q++) acc[i][j][q] = 0.f;

    // stage loader: A 512 chunks(16B), B 1024 chunks -> 3 cp16/thread
    auto load_stage = [&](int s, int buf) {
        const uint32_t st = sbase + buf * STAGE_BYTES;
        const int k0 = s * BK;
        {
            int r = tid >> 2, q = tid & 3;              // A: 512 chunks
            uint32_t so = (uint32_t)(r * PITCH + q * 16);
            cp16(st + so, A + (size_t)(aRow0 + r) * lda + k0 + q * 8);
        }
#pragma unroll
        for (int i = 0; i < 2; i++) {                   // B: 1024 chunks
            int c = tid + i * NTHREADS;
            int r = c >> 2, q = c & 3;
            uint32_t so = (uint32_t)(r * PITCH + q * 16);
            cp16(st + OFF_B + so, B + (size_t)(bRow0 + r) * ldb + k0 + q * 8);
        }
    };

    // lane-fixed parts of ldmatrix addresses
    const uint32_t aLane = (uint32_t)((wm * 32 + (lane & 15)) * PITCH + (lane >> 4) * 16);
    const uint32_t bLane = (uint32_t)((wn * 64 + (lane & 15)) * PITCH + (lane >> 4) * 16);

    load_stage(0, 0); CP_COMMIT();
    load_stage(1, 1); CP_COMMIT();

    for (int s = 0; s < S; s++) {
        if (s + 2 < S) load_stage(s + 2, (s + 2) % NSTAGE);
        CP_COMMIT();
        CP_WAIT2();
        __syncthreads();

        const uint32_t st = sbase + (s % NSTAGE) * STAGE_BYTES;
#pragma unroll
        for (int ks = 0; ks < 2; ks++) {               // two k16 steps per stage
            const uint32_t kOff = (uint32_t)(ks * 32); // 16 elems * 2B
            uint32_t ah[2][4], bx[8][2];
#pragma unroll
            for (int i = 0; i < 2; i++) {
                uint32_t ad = st + aLane + kOff + (uint32_t)(i * 16 * PITCH);
                ldsm4(ah[i][0], ah[i][1], ah[i][2], ah[i][3], ad);
            }
#pragma unroll
            for (int jj = 0; jj < 4; jj++) {
                uint32_t bd = st + OFF_B + bLane + kOff + (uint32_t)(jj * 16 * PITCH);
                uint32_t r0, r1, r2, r3;
                ldsm4(r0, r1, r2, r3, bd);
                bx[jj * 2 + 0][0] = r0; bx[jj * 2 + 1][0] = r1;
                bx[jj * 2 + 0][1] = r2; bx[jj * 2 + 1][1] = r3;
            }
#pragma unroll
            for (int i = 0; i < 2; i++)
#pragma unroll
                for (int j = 0; j < 8; j++) mma16816(acc[i][j], ah[i], bx[j]);
        }
        __syncthreads();
    }

    // ---- epilogue (register -> global) ------------------------------------
    const int rBase = aRow0 + wm * 32 + (lane >> 2);
    const int cBase = col0 + wn * 64 + 2 * (lane & 3);
    if (MODE == 0) {
        uint32_t* gH = reinterpret_cast<uint32_t*>(Hc);
#pragma unroll
        for (int i = 0; i < 2; i++)
#pragma unroll
            for (int j = 0; j < 8; j++) {
                int r0 = rBase + i * 16;
                int c  = cBase + j * 8;
                float v0 = fmaxf(acc[i][j][0], 0.f), v1 = fmaxf(acc[i][j][1], 0.f);
                float v2 = fmaxf(acc[i][j][2], 0.f), v3 = fmaxf(acc[i][j][3], 0.f);
                size_t w0 = ((size_t)r0 * FF_ + c) >> 1;
                size_t w1 = ((size_t)(r0 + 8) * FF_ + c) >> 1;
                gH[w0] = pack2h(__float2half(v0), __float2half(v1));
                gH[w1] = pack2h(__float2half(v2), __float2half(v3));
            }
    } else {
#pragma unroll
        for (int i = 0; i < 2; i++)
#pragma unroll
            for (int j = 0; j < 8; j++) {
                int r0 = rBase + i * 16;
                int c  = cBase + j * 8;
                float2 p0 = make_float2(acc[i][j][0], acc[i][j][1]);
                float2 p1 = make_float2(acc[i][j][2], acc[i][j][3]);
                *reinterpret_cast<float2*>(&Cf[(size_t)r0 * H_ + c])       = p0;
                *reinterpret_cast<float2*>(&Cf[(size_t)(r0 + 8) * H_ + c]) = p1;
            }
    }
}

// ---------------------------------------------------------------------------
// Host launcher
// ---------------------------------------------------------------------------
extern "C" void kernel_launch(void* const* d_in, const int* in_sizes, int n_in,
                              void* d_out, int out_size) {
    (void)in_sizes; (void)n_in; (void)out_size;
    const float* x  = (const float*)d_in[0];
    const float* w1 = (const float*)d_in[1];
    const float* w2 = (const float*)d_in[2];
    float* out = (float*)d_out;

    void *xh, *w1h, *w2th, *hh;
    cudaGetSymbolAddress(&xh,  g_XH);
    cudaGetSymbolAddress(&w1h, g_W1H);
    cudaGetSymbolAddress(&w2th, g_W2TH);
    cudaGetSymbolAddress(&hh,  g_HH);

    cudaFuncSetAttribute(gemm_h1<1024, 0>,
                         cudaFuncAttributeMaxDynamicSharedMemorySize, SMEM_TOTAL);
    cudaFuncSetAttribute(gemm_h1<4096, 1>,
                         cudaFuncAttributeMaxDynamicSharedMemorySize, SMEM_TOTAL);

    // 1) fp32 -> fp16 casts
    tohalf_kernel<<<2048, 256>>>(x, (__half*)xh, T_ * H_ / 4);
    tohalf_kernel<<<2048, 256>>>(w1, (__half*)w1h, E_ * FF_ * H_ / 4);
    transpose_half<<<dim3(H_ / 32, FF_ / 32, E_), dim3(32, 8)>>>(w2, (__half*)w2th);

    // 2) GEMM1: h = relu(x @ w1^T) -> fp16; A ld=H, B ld=H, expert stride FF
    gemm_h1<1024, 0><<<dim3(FF_ / BN, G_ / BM, E_), NTHREADS, SMEM_TOTAL>>>(
        (const __half*)xh, H_,
        (const __half*)w1h, H_, FF_,
        (__half*)hh, nullptr);

    // 3) GEMM2: out = h @ w2 (w2 pre-transposed -> TN); A ld=FF, B ld=FF, stride H
    gemm_h1<4096, 1><<<dim3(H_ / BN, G_ / BM, E_), NTHREADS, SMEM_TOTAL>>>(
        (const __half*)hh, FF_,
        (const __half*)w2th, FF_, H_,
        nullptr, out);
}